// round 16
// baseline (speedup 1.0000x reference)
#include <cuda_runtime.h>
#include <cuda_bf16.h>
#include <math.h>
#include <stdint.h>

#define Bc 4
#define Sc 2048
#define Dc 512
#define Nc 16
#define DTR 32
#define BS (Bc*Sc)
#define BSD (BS*Dc)
#define CL 32
#define NCH (Sc/CL)
#define NSCAN (Bc*NCH*Dc*Nc)
#define NFU 1152               // fused N: 512 z1 + 512 bwd + 64 dbc + 64 pad

// ---- fp32 scratch ----
__device__ float g_z1[BSD];
__device__ float g_bwd[BSD];
__device__ float g_dbc[BS*64];
__device__ float g_p[BSD];
__device__ float g_du[BSD];
__device__ float g_afin[NSCAN];   // reused: wgemmC fp32 out (512x512)
__device__ float g_hfin[NSCAN];   // reused: wgemmB fp32 out (64x512)
__device__ float g_h0[NSCAN];
__device__ float g_biasf[NFU];

// ---- split-bf16 operand buffers ----
__device__ __nv_bfloat16 g_xnh[BSD],  g_xnl[BSD];
__device__ __nv_bfloat16 g_dbch[BS*64], g_dbcl[BS*64];
__device__ __nv_bfloat16 g_wfh[NFU*Dc], g_wfl[NFU*Dc];      // fused weights (pad rows stay 0)
__device__ __nv_bfloat16 g_wprm[Dc*Dc], g_wprml[Dc*Dc];     // W_proj row-major split
__device__ __nv_bfloat16 g_wbh[Dc*Dc], g_wbl[Dc*Dc];        // W_bwd^T split
__device__ __nv_bfloat16 g_wpbrmh[Dc*Dc], g_wpbrml[Dc*Dc];  // Wpb row-major split
__device__ __nv_bfloat16 g_wdbch[64*Dc], g_wdbcl[64*Dc];
__device__ __nv_bfloat16 g_wdth[Dc*DTR], g_wdtl[Dc*DTR];

// =====================================================================
// helpers
// =====================================================================
__device__ __forceinline__ void split1(float v, __nv_bfloat16& h, __nv_bfloat16& l)
{
    h = __float2bfloat16(v);
    l = __float2bfloat16(v - __bfloat162float(h));
}

__device__ __forceinline__ void mma16816(float* c, const uint32_t* a, const uint32_t* b)
{
    asm volatile(
        "mma.sync.aligned.m16n8k16.row.col.f32.bf16.bf16.f32 "
        "{%0,%1,%2,%3}, {%4,%5,%6,%7}, {%8,%9}, {%0,%1,%2,%3};\n"
        : "+f"(c[0]), "+f"(c[1]), "+f"(c[2]), "+f"(c[3])
        : "r"(a[0]), "r"(a[1]), "r"(a[2]), "r"(a[3]),
          "r"(b[0]), "r"(b[1]));
}

__device__ __forceinline__ void ldsm_x4(uint32_t* r, uint32_t addr)
{
    asm volatile("ldmatrix.sync.aligned.m8n8.x4.shared.b16 {%0,%1,%2,%3}, [%4];\n"
                 : "=r"(r[0]), "=r"(r[1]), "=r"(r[2]), "=r"(r[3]) : "r"(addr));
}

__device__ __forceinline__ void ldsm_x2(uint32_t* r, uint32_t addr)
{
    asm volatile("ldmatrix.sync.aligned.m8n8.x2.shared.b16 {%0,%1}, [%2];\n"
                 : "=r"(r[0]), "=r"(r[1]) : "r"(addr));
}

__device__ __forceinline__ void cp16(uint32_t dst_smem, const void* src_gmem)
{
    asm volatile("cp.async.ca.shared.global [%0], [%1], 16;\n"
                 :: "r"(dst_smem), "l"(src_gmem) : "memory");
}
#define CP_COMMIT() asm volatile("cp.async.commit_group;\n" ::: "memory")
#define CP_WAIT0()  asm volatile("cp.async.wait_group 0;\n" ::: "memory")

__device__ __forceinline__ int swz(int row, int kc)
{
    return row * 4 + (kc ^ ((row >> 1) & 3));
}

__device__ __forceinline__ void pow16n(float pv, float* dA)
{
    float p1 = pv, p2 = p1*p1, p4 = p2*p2, p8 = p4*p4;
    dA[0]=p1;        dA[1]=p2;        dA[2]=p2*p1;     dA[3]=p4;
    dA[4]=p4*p1;     dA[5]=p4*p2;     dA[6]=p4*dA[2];  dA[7]=p8;
    dA[8]=p8*p1;     dA[9]=p8*p2;     dA[10]=p8*dA[2]; dA[11]=p8*p4;
    dA[12]=p8*dA[4]; dA[13]=p8*dA[5]; dA[14]=p8*dA[6]; dA[15]=p8*p8;
}

// =====================================================================
// weight converts
// =====================================================================
__global__ void convert_w(const float* __restrict__ W, int K, int N,
                          __nv_bfloat16* __restrict__ oh,
                          __nv_bfloat16* __restrict__ ol)
{
    int idx = blockIdx.x * blockDim.x + threadIdx.x;
    if (idx >= K * N) return;
    int k = idx / N, n = idx % N;
    __nv_bfloat16 h, l;
    split1(W[idx], h, l);
    oh[n * K + k] = h;
    ol[n * K + k] = l;
}

__global__ void convert_rm(const float* __restrict__ W, int total,
                           __nv_bfloat16* __restrict__ oh,
                           __nv_bfloat16* __restrict__ ol)
{
    int idx = blockIdx.x * blockDim.x + threadIdx.x;
    if (idx >= total) return;
    __nv_bfloat16 h, l;
    split1(W[idx], h, l);
    oh[idx] = h;
    ol[idx] = l;
}

// transpose + split: src[k][j] (512x512 fp32) -> oh[j*512+k]
__global__ void transpose_split(const float* __restrict__ src,
                                __nv_bfloat16* __restrict__ oh,
                                __nv_bfloat16* __restrict__ ol)
{
    int idx = blockIdx.x * blockDim.x + threadIdx.x;   // 262144
    int j = idx & 511, k = idx >> 9;
    float v = src[k * 512 + j];
    __nv_bfloat16 h, l;
    split1(v, h, l);
    oh[j * 512 + k] = h;
    ol[j * 512 + k] = l;
}

// biasf stage 1: [0,512)=b_proj ; [512,1024)= b_proj? no: bias for bwd cols
// bwd = xn@Wpb + (bp@Wb + bb). z1 bias = bp.
__global__ void bias2_kernel(const float* __restrict__ b_proj,
                             const float* __restrict__ W_bwd,
                             const float* __restrict__ b_bwd,
                             float* __restrict__ biasf)
{
    int n = threadIdx.x;   // 512
    biasf[n] = b_proj[n];
    float s = b_bwd[n];
    for (int j = 0; j < 512; j++)
        s = fmaf(b_proj[j], W_bwd[j * 512 + n], s);
    biasf[512 + n] = s;
}
// biasf stage 2: [1024,1088) = bias2 @ W_dbc ; [1088,1152) = 0
__global__ void bias3_kernel(const float* __restrict__ W_dbc,
                             float* __restrict__ biasf)
{
    int c = threadIdx.x;   // 128
    if (c < 64) {
        float s = 0.f;
        for (int j = 0; j < 512; j++)
            s = fmaf(biasf[512 + j], W_dbc[j * 64 + c], s);
        biasf[1024 + c] = s;
    } else {
        biasf[1024 + c] = 0.f;
    }
}

// =====================================================================
// LayerNorm -> split bf16
// =====================================================================
__global__ void ln_kernel(const float* __restrict__ x,
                          const float* __restrict__ gamma,
                          const float* __restrict__ beta,
                          __nv_bfloat16* __restrict__ xnh,
                          __nv_bfloat16* __restrict__ xnl)
{
    int row = blockIdx.x;
    int tid = threadIdx.x;
    const float4* xr = reinterpret_cast<const float4*>(x + (size_t)row * Dc);
    float4 v = xr[tid];
    float s = v.x + v.y + v.z + v.w;
    float q = v.x*v.x + v.y*v.y + v.z*v.z + v.w*v.w;
    #pragma unroll
    for (int o = 16; o; o >>= 1) {
        s += __shfl_xor_sync(0xffffffffu, s, o);
        q += __shfl_xor_sync(0xffffffffu, q, o);
    }
    __shared__ float ss[4], sq[4];
    if ((tid & 31) == 0) { ss[tid >> 5] = s; sq[tid >> 5] = q; }
    __syncthreads();
    s = ss[0] + ss[1] + ss[2] + ss[3];
    q = sq[0] + sq[1] + sq[2] + sq[3];
    float mean = s * (1.0f / Dc);
    float var  = q * (1.0f / Dc) - mean * mean;
    float rstd = rsqrtf(var + 1e-5f);
    float4 g  = reinterpret_cast<const float4*>(gamma)[tid];
    float4 bt = reinterpret_cast<const float4*>(beta)[tid];
    float ov[4];
    ov[0] = (v.x - mean) * rstd * g.x + bt.x;
    ov[1] = (v.y - mean) * rstd * g.y + bt.y;
    ov[2] = (v.z - mean) * rstd * g.z + bt.z;
    ov[3] = (v.w - mean) * rstd * g.w + bt.w;
    size_t base = (size_t)row * Dc + tid * 4;
    #pragma unroll
    for (int j = 0; j < 4; j++) {
        __nv_bfloat16 h, l;
        split1(ov[j], h, l);
        xnh[base + j] = h;
        xnl[base + j] = l;
    }
}

// =====================================================================
// v8: BM=128 x BN=128 GEMM, 4 warps, dyn smem 64KB
// EPI 1: dt epilogue (R13 form). EPI 4: fused [z1|bwd|dbc] scatter
// =====================================================================
template<int EPI>
__global__ __launch_bounds__(128, 2)
void mma_gemm8(const __nv_bfloat16* __restrict__ Ah,
               const __nv_bfloat16* __restrict__ Al, int lda,
               const __nv_bfloat16* __restrict__ Bh,
               const __nv_bfloat16* __restrict__ Bl, int ldb,
               const float* __restrict__ bias,
               float* __restrict__ C0, float* __restrict__ C1,
               const float* __restrict__ aux,
               float* __restrict__ C2,
               __nv_bfloat16* __restrict__ C0h,
               __nv_bfloat16* __restrict__ C0l,
               int M, int N, int K)
{
    constexpr int BM = 128, BN = 128;
    extern __shared__ __align__(16) uint4 dsm[];
    uint4* sAh = dsm;
    uint4* sAl = dsm + 2 * BM * 4;
    uint4* sBh = dsm + 4 * BM * 4;
    uint4* sBl = dsm + 4 * BM * 4 + 2 * BN * 4;

    uint32_t aAh = (uint32_t)__cvta_generic_to_shared(sAh);
    uint32_t aAl = (uint32_t)__cvta_generic_to_shared(sAl);
    uint32_t aBh = (uint32_t)__cvta_generic_to_shared(sBh);
    uint32_t aBl = (uint32_t)__cvta_generic_to_shared(sBl);

    int tid = threadIdx.x;
    int bm = blockIdx.y * BM;
    int bn = blockIdx.x * BN;
    int wid = tid >> 5, l = tid & 31;
    int wn = wid & 1, wm = wid >> 1;
    int m_off = wm * 64;
    int n_off = wn * 64;

    float acc[4][8][4];
    #pragma unroll
    for (int i = 0; i < 4; i++)
        #pragma unroll
        for (int j = 0; j < 8; j++)
            #pragma unroll
            for (int c = 0; c < 4; c++) acc[i][j][c] = 0.f;

    auto issue_tile = [&](int k0, int buf) {
        #pragma unroll
        for (int r = 0; r < 4; r++) {
            int v = tid + r * 128;
            int m = v >> 2, kc = v & 3;
            uint32_t dst = (uint32_t)((buf * BM * 4 + swz(m, kc)) * 16);
            cp16(aAh + dst, Ah + (size_t)(bm + m) * lda + k0 + kc * 8);
            cp16(aAl + dst, Al + (size_t)(bm + m) * lda + k0 + kc * 8);
        }
        #pragma unroll
        for (int r = 0; r < 4; r++) {
            int v = tid + r * 128;
            int n = v >> 2, kc = v & 3;
            uint32_t dst = (uint32_t)((buf * BN * 4 + swz(n, kc)) * 16);
            cp16(aBh + dst, Bh + (size_t)(bn + n) * ldb + k0 + kc * 8);
            cp16(aBl + dst, Bl + (size_t)(bn + n) * ldb + k0 + kc * 8);
        }
        CP_COMMIT();
    };

    issue_tile(0, 0);

    int buf = 0;
    for (int k0 = 0; k0 < K; k0 += 32) {
        bool has_next = (k0 + 32 < K);
        CP_WAIT0();
        __syncthreads();
        if (has_next) issue_tile(k0 + 32, buf ^ 1);

        int bofA = buf * BM * 4;
        int bofB = buf * BN * 4;
        #pragma unroll
        for (int ks = 0; ks < 2; ks++) {
            uint32_t ah[4][4], alo[4][4];
            #pragma unroll
            for (int im = 0; im < 4; im++) {
                int row = m_off + im * 16 + (l & 15);
                int kc = ks * 2 + (l >> 4);
                ldsm_x4(ah[im],  aAh + (bofA + swz(row, kc)) * 16);
                ldsm_x4(alo[im], aAl + (bofA + swz(row, kc)) * 16);
            }
            uint32_t bh2[8][2], bl2[8][2];
            #pragma unroll
            for (int in = 0; in < 8; in++) {
                int row = n_off + in * 8 + (l & 7);
                int kc = ks * 2 + ((l >> 3) & 1);
                ldsm_x2(bh2[in], aBh + (bofB + swz(row, kc)) * 16);
                ldsm_x2(bl2[in], aBl + (bofB + swz(row, kc)) * 16);
            }
            #pragma unroll
            for (int im = 0; im < 4; im++)
                #pragma unroll
                for (int in = 0; in < 8; in++) {
                    mma16816(acc[im][in], ah[im],  bh2[in]);
                    mma16816(acc[im][in], alo[im], bh2[in]);
                    mma16816(acc[im][in], ah[im],  bl2[in]);
                }
        }
        if (has_next) buf ^= 1;
    }

    // ---- epilogue ----
    #pragma unroll
    for (int im = 0; im < 4; im++) {
        int r0 = bm + m_off + im * 16 + (l >> 2);
        #pragma unroll
        for (int in = 0; in < 8; in++) {
            int n = bn + n_off + in * 8 + 2 * (l & 3);
            float b0 = bias ? __ldg(bias + n)     : 0.f;
            float b1 = bias ? __ldg(bias + n + 1) : 0.f;
            float vv[4];
            vv[0] = acc[im][in][0] + b0;
            vv[1] = acc[im][in][1] + b1;
            vv[2] = acc[im][in][2] + b0;
            vv[3] = acc[im][in][3] + b1;
            int rr[4] = {r0, r0, r0 + 8, r0 + 8};
            int cc[4] = {n, n + 1, n, n + 1};
            if (EPI == 1) {
                #pragma unroll
                for (int e = 0; e < 4; e++) {
                    size_t idx = (size_t)rr[e] * N + cc[e];
                    float v = vv[e];
                    float p, dlt;
                    if (v > 15.f) { p = __expf(-v); dlt = v; }
                    else {
                        float ev = __expf(v);
                        p = __fdividef(1.f, 1.f + ev);
                        dlt = __logf(1.f + ev);
                    }
                    C0[idx] = p;
                    C1[idx] = dlt * __ldg(aux + idx);
                }
            } else { // EPI == 4: fused [z1 | bwd | dbc]
                #pragma unroll
                for (int e = 0; e < 4; e++) {
                    int nn = cc[e], m = rr[e];
                    float v = vv[e];
                    if (nn < 512) {
                        C0[(size_t)m * 512 + nn] = v;          // z1
                    } else if (nn < 1024) {
                        C1[(size_t)m * 512 + (nn - 512)] = v;  // bwd
                    } else if (nn < 1088) {
                        size_t id = (size_t)m * 64 + (nn - 1024);
                        C2[id] = v;                             // dbc fp32
                        __nv_bfloat16 h, lo;
                        split1(v, h, lo);
                        C0h[id] = h;
                        C0l[id] = lo;
                    }
                }
            }
        }
    }
}

// =====================================================================
// v7 64x64 GEMM (proven) — weight-product GEMMs
// =====================================================================
template<int BM, int BN, int WMT, int WNT, int NTHR>
__global__ __launch_bounds__(NTHR, 3)
void mma_gemm7(const __nv_bfloat16* __restrict__ Ah,
               const __nv_bfloat16* __restrict__ Al, int lda,
               const __nv_bfloat16* __restrict__ Bh,
               const __nv_bfloat16* __restrict__ Bl, int ldb,
               const float* __restrict__ bias,
               float* __restrict__ C0,
               __nv_bfloat16* __restrict__ C0h,
               __nv_bfloat16* __restrict__ C0l,
               int M, int N, int K)
{
    constexpr int WARPS_N = BN / (WNT * 8);
    constexpr int A_CH = (BM * 4) / NTHR;
    constexpr int B_CH = (BN * 4) / NTHR;

    __shared__ __align__(16) uint4 sAh[2 * BM * 4];
    __shared__ __align__(16) uint4 sAl[2 * BM * 4];
    __shared__ __align__(16) uint4 sBh[2 * BN * 4];
    __shared__ __align__(16) uint4 sBl[2 * BN * 4];

    uint32_t aAh = (uint32_t)__cvta_generic_to_shared(sAh);
    uint32_t aAl = (uint32_t)__cvta_generic_to_shared(sAl);
    uint32_t aBh = (uint32_t)__cvta_generic_to_shared(sBh);
    uint32_t aBl = (uint32_t)__cvta_generic_to_shared(sBl);

    int tid = threadIdx.x;
    int bm = blockIdx.y * BM;
    int bn = blockIdx.x * BN;
    int wid = tid >> 5, l = tid & 31;
    int wn = wid % WARPS_N, wm = wid / WARPS_N;
    int m_off = wm * (WMT * 16);
    int n_off = wn * (WNT * 8);

    float acc[WMT][WNT][4];
    #pragma unroll
    for (int i = 0; i < WMT; i++)
        #pragma unroll
        for (int j = 0; j < WNT; j++)
            #pragma unroll
            for (int c = 0; c < 4; c++) acc[i][j][c] = 0.f;

    auto issue_tile = [&](int k0, int buf) {
        #pragma unroll
        for (int r = 0; r < A_CH; r++) {
            int v = tid + r * NTHR;
            int m = v >> 2, kc = v & 3;
            uint32_t dst = (uint32_t)((buf * BM * 4 + swz(m, kc)) * 16);
            cp16(aAh + dst, Ah + (size_t)(bm + m) * lda + k0 + kc * 8);
            cp16(aAl + dst, Al + (size_t)(bm + m) * lda + k0 + kc * 8);
        }
        #pragma unroll
        for (int r = 0; r < B_CH; r++) {
            int v = tid + r * NTHR;
            int n = v >> 2, kc = v & 3;
            uint32_t dst = (uint32_t)((buf * BN * 4 + swz(n, kc)) * 16);
            cp16(aBh + dst, Bh + (size_t)(bn + n) * ldb + k0 + kc * 8);
            cp16(aBl + dst, Bl + (size_t)(bn + n) * ldb + k0 + kc * 8);
        }
        CP_COMMIT();
    };

    issue_tile(0, 0);

    int buf = 0;
    for (int k0 = 0; k0 < K; k0 += 32) {
        bool has_next = (k0 + 32 < K);
        CP_WAIT0();
        __syncthreads();
        if (has_next) issue_tile(k0 + 32, buf ^ 1);

        int bofA = buf * BM * 4;
        int bofB = buf * BN * 4;
        uint32_t bhf[WNT][4], blf[WNT][4];
        #pragma unroll
        for (int in = 0; in < WNT; in++) {
            int row = n_off + in * 8 + (l & 7);
            int kc = l >> 3;
            ldsm_x4(bhf[in], aBh + (bofB + swz(row, kc)) * 16);
            ldsm_x4(blf[in], aBl + (bofB + swz(row, kc)) * 16);
        }
        #pragma unroll
        for (int ks = 0; ks < 2; ks++) {
            uint32_t ah[WMT][4], alo[WMT][4];
            #pragma unroll
            for (int im = 0; im < WMT; im++) {
                int row = m_off + im * 16 + (l & 15);
                int kc = ks * 2 + (l >> 4);
                ldsm_x4(ah[im],  aAh + (bofA + swz(row, kc)) * 16);
                ldsm_x4(alo[im], aAl + (bofA + swz(row, kc)) * 16);
            }
            #pragma unroll
            for (int im = 0; im < WMT; im++)
                #pragma unroll
                for (int in = 0; in < WNT; in++) {
                    uint32_t bhk[2] = {bhf[in][2*ks], bhf[in][2*ks+1]};
                    uint32_t blk[2] = {blf[in][2*ks], blf[in][2*ks+1]};
                    mma16816(acc[im][in], ah[im], bhk);
                    mma16816(acc[im][in], alo[im], bhk);
                    mma16816(acc[im][in], ah[im], blk);
                }
        }
        if (has_next) buf ^= 1;
    }

    #pragma unroll
    for (int im = 0; im < WMT; im++) {
        int r0 = bm + m_off + im * 16 + (l >> 2);
        #pragma unroll
        for (int in = 0; in < WNT; in++) {
            int n = bn + n_off + in * 8 + 2 * (l & 3);
            float b0 = bias ? __ldg(bias + n)     : 0.f;
            float b1 = bias ? __ldg(bias + n + 1) : 0.f;
            float vv[4];
            vv[0] = acc[im][in][0] + b0;
            vv[1] = acc[im][in][1] + b1;
            vv[2] = acc[im][in][2] + b0;
            vv[3] = acc[im][in][3] + b1;
            size_t i00 = (size_t)r0 * N + n;
            size_t i10 = (size_t)(r0 + 8) * N + n;
            size_t ii[4] = {i00, i00 + 1, i10, i10 + 1};
            #pragma unroll
            for (int e = 0; e < 4; e++) {
                C0[ii[e]] = vv[e];
                if (C0h) {
                    __nv_bfloat16 h, lo;
                    split1(vv[e], h, lo);
                    C0h[ii[e]] = h;
                    C0l[ii[e]] = lo;
                }
            }
        }
    }
}

// =====================================================================
// Scan v3 (R13 exact, passing)
// =====================================================================
__device__ __forceinline__ bool a_is_np1(const float* A_log, int d)
{
    bool ok = true;
    #pragma unroll
    for (int n = 0; n < 16; n++) {
        float af = __expf(__ldg(A_log + d * Nc + n));
        float r = rintf(af);
        if (!(fabsf(af - r) < 1e-4f * af) || (int)r != n + 1) ok = false;
    }
    return ok;
}

__global__ __launch_bounds__(256, 2)
void scan_passA2(const float* __restrict__ p,
                 const float* __restrict__ du,
                 const float* __restrict__ dbc,
                 const float* __restrict__ A_log,
                 float* __restrict__ afin,
                 float* __restrict__ hfin)
{
    int bid = blockIdx.x;
    int dg = bid & 1;
    int ch = (bid >> 1) & (NCH - 1);
    int b  = bid / (2 * NCH);
    int d  = dg * 256 + threadIdx.x;

    __shared__ float4 sB[CL][4];
    int srow = b * Sc + ch * CL;
    {
        int i = threadIdx.x;
        if (i < CL * 4) {
            int s = i >> 2, j = i & 3;
            sB[s][j] = *reinterpret_cast<const float4*>(
                dbc + (size_t)(srow + s) * 64 + DTR + j * 4);
        }
    }
    __syncthreads();

    bool np1 = a_is_np1(A_log, d);

    float h[16];
    #pragma unroll
    for (int n = 0; n < 16; n++) h[n] = 0.f;
    float P = 1.f;

    size_t base = (size_t)srow * Dc + d;
    if (np1) {
        #pragma unroll 2
        for (int s = 0; s < CL; ++s) {
            float pv  = p[base];
            float duv = du[base];
            const float* Bv = reinterpret_cast<const float*>(&sB[s][0]);
            float dA[16];
            pow16n(pv, dA);
            P *= pv;
            #pragma unroll
            for (int n = 0; n < 16; n++)
                h[n] = fmaf(dA[n], h[n], duv * Bv[n]);
            base += Dc;
        }
        float Pn[16];
        pow16n(P, Pn);
        size_t t16 = ((size_t)(b * NCH + ch) * Dc + d) * 16;
        float4* ao = reinterpret_cast<float4*>(afin + t16);
        float4* ho = reinterpret_cast<float4*>(hfin + t16);
        #pragma unroll
        for (int q = 0; q < 4; q++) {
            ao[q] = make_float4(Pn[4*q], Pn[4*q+1], Pn[4*q+2], Pn[4*q+3]);
            ho[q] = make_float4(h[4*q],  h[4*q+1],  h[4*q+2],  h[4*q+3]);
        }
    } else {
        float aprod[16];
        #pragma unroll
        for (int n = 0; n < 16; n++) aprod[n] = 1.f;
        for (int s = 0; s < CL; ++s) {
            float pv  = p[base];
            float duv = du[base];
            const float* Bv = reinterpret_cast<const float*>(&sB[s][0]);
            for (int n = 0; n < 16; n++) {
                float af = __expf(__ldg(A_log + d * Nc + n));
                float dA = __powf(pv, af);
                aprod[n] *= dA;
                h[n] = fmaf(dA, h[n], duv * Bv[n]);
            }
            base += Dc;
        }
        size_t t16 = ((size_t)(b * NCH + ch) * Dc + d) * 16;
        for (int n = 0; n < 16; n++) {
            afin[t16 + n] = aprod[n];
            hfin[t16 + n] = h[n];
        }
    }
}

__global__ __launch_bounds__(256)
void scan_mid(const float* __restrict__ afin,
              const float* __restrict__ hfin,
              float* __restrict__ h0)
{
    int t = blockIdx.x * blockDim.x + threadIdx.x;
    int dn = t & (Dc * 16 - 1);
    int b  = t >> 13;
    float run = 0.f;
    #pragma unroll 4
    for (int ch = 0; ch < NCH; ++ch) {
        int tt = ((b * NCH + ch) * Dc * 16) + dn;
        h0[tt] = run;
        run = fmaf(__ldg(afin + tt), run, __ldg(hfin + tt));
    }
}

__global__ __launch_bounds__(256, 2)
void scan_passB2(const float* __restrict__ p,
                 const float* __restrict__ du,
                 const float* __restrict__ dbc,
                 const float* __restrict__ h0,
                 const float* __restrict__ u,
                 const float* __restrict__ z1,
                 const float* __restrict__ x,
                 const float* __restrict__ A_log,
                 const float* __restrict__ D_ssm,
                 float* __restrict__ out)
{
    int bid = blockIdx.x;
    int dg = bid & 1;
    int ch = (bid >> 1) & (NCH - 1);
    int b  = bid / (2 * NCH);
    int d  = dg * 256 + threadIdx.x;

    __shared__ float4 sB[CL][4];
    __shared__ float4 sC[CL][4];
    int srow = b * Sc + ch * CL;
    {
        int i = threadIdx.x;
        int s = i >> 3, j = i & 7;
        float4 v = *reinterpret_cast<const float4*>(
            dbc + (size_t)(srow + s) * 64 + DTR + j * 4);
        if (j < 4) sB[s][j] = v;
        else       sC[s][j - 4] = v;
    }
    __syncthreads();

    bool np1 = a_is_np1(A_log, d);
    float Dd = __ldg(D_ssm + d);

    size_t t16 = ((size_t)(b * NCH + ch) * Dc + d) * 16;
    float h[16];
    {
        const float4* hi = reinterpret_cast<const float4*>(h0 + t16);
        #pragma unroll
        for (int q = 0; q < 4; q++) {
            float4 v = hi[q];
            h[4*q] = v.x; h[4*q+1] = v.y; h[4*q+2] = v.z; h[4*q+3] = v.w;
        }
    }

    size_t base = (size_t)srow * Dc + d;
    if (np1) {
        #pragma unroll 2
        for (int s = 0; s < CL; ++s) {
            float pv  = p[base];
            float duv = du[base];
            const float* Bv = reinterpret_cast<const float*>(&sB[s][0]);
            const float* Cv = reinterpret_cast<const float*>(&sC[s][0]);
            float dA[16];
            pow16n(pv, dA);
            float y0 = 0.f, y1 = 0.f;
            #pragma unroll
            for (int n = 0; n < 16; n++) {
                h[n] = fmaf(dA[n], h[n], duv * Bv[n]);
                if (n & 1) y1 = fmaf(h[n], Cv[n], y1);
                else       y0 = fmaf(h[n], Cv[n], y0);
            }
            float y = y0 + y1;
            float uv = u[base];
            float zv = z1[base];
            float xv = x[base];
            float x2v = y + Dd * uv;
            float sil = __fdividef(zv, 1.f + __expf(-zv));
            out[base] = (zv + x2v) * sil + xv;
            base += Dc;
        }
    } else {
        for (int s = 0; s < CL; ++s) {
            float pv  = p[base];
            float duv = du[base];
            const float* Bv = reinterpret_cast<const float*>(&sB[s][0]);
            const float* Cv = reinterpret_cast<const float*>(&sC[s][0]);
            float y = 0.f;
            for (int n = 0; n < 16; n++) {
                float af = __expf(__ldg(A_log + d * Nc + n));
                float dA = __powf(pv, af);
                h[n] = fmaf(dA, h[n], duv * Bv[n]);
                y = fmaf(h[n], Cv[n], y);
            }
            float uv = u[base];
            float zv = z1[base];
            float xv = x[base];
            float x2v = y + Dd * uv;
            float sil = __fdividef(zv, 1.f + __expf(-zv));
            out[base] = (zv + x2v) * sil + xv;
            base += Dc;
        }
    }
}

// =====================================================================
// launch
// =====================================================================
#define V8_SMEM (4 * 2 * 128 * 4 * 16)   // 65536 bytes

extern "C" void kernel_launch(void* const* d_in, const int* in_sizes, int n_in,
                              void* d_out, int out_size)
{
    const float* x      = (const float*)d_in[0];
    const float* gamma  = (const float*)d_in[1];
    const float* beta   = (const float*)d_in[2];
    const float* W_proj = (const float*)d_in[3];
    const float* b_proj = (const float*)d_in[4];
    // d_in[5] W_fwd, d_in[6] b_fwd: dead code (x1_ssm unused in reference)
    const float* W_bwd  = (const float*)d_in[7];
    const float* b_bwd  = (const float*)d_in[8];
    const float* W_dbc  = (const float*)d_in[9];
    const float* W_dt   = (const float*)d_in[10];
    const float* b_dt   = (const float*)d_in[11];
    const float* A_log  = (const float*)d_in[12];
    const float* D_ssm  = (const float*)d_in[13];
    float* out = (float*)d_out;

    static bool init = false;
    static float *p_z1, *p_bwd, *p_dbc, *p_p, *p_du, *p_afin, *p_hfin, *p_h0,
                 *p_biasf;
    static __nv_bfloat16 *p_xnh, *p_xnl, *p_dbch, *p_dbcl,
                         *p_wfh, *p_wfl, *p_wprm, *p_wprml, *p_wbh, *p_wbl,
                         *p_wpbrmh, *p_wpbrml,
                         *p_wdbch, *p_wdbcl, *p_wdth, *p_wdtl;
    if (!init) {
        void* v;
        cudaGetSymbolAddress(&v, g_z1);      p_z1     = (float*)v;
        cudaGetSymbolAddress(&v, g_bwd);     p_bwd    = (float*)v;
        cudaGetSymbolAddress(&v, g_dbc);     p_dbc    = (float*)v;
        cudaGetSymbolAddress(&v, g_p);       p_p      = (float*)v;
        cudaGetSymbolAddress(&v, g_du);      p_du     = (float*)v;
        cudaGetSymbolAddress(&v, g_afin);    p_afin   = (float*)v;
        cudaGetSymbolAddress(&v, g_hfin);    p_hfin   = (float*)v;
        cudaGetSymbolAddress(&v, g_h0);      p_h0     = (float*)v;
        cudaGetSymbolAddress(&v, g_biasf);   p_biasf  = (float*)v;
        cudaGetSymbolAddress(&v, g_xnh);     p_xnh    = (__nv_bfloat16*)v;
        cudaGetSymbolAddress(&v, g_xnl);     p_xnl    = (__nv_bfloat16*)v;
        cudaGetSymbolAddress(&v, g_dbch);    p_dbch   = (__nv_bfloat16*)v;
        cudaGetSymbolAddress(&v, g_dbcl);    p_dbcl   = (__nv_bfloat16*)v;
        cudaGetSymbolAddress(&v, g_wfh);     p_wfh    = (__nv_bfloat16*)v;
        cudaGetSymbolAddress(&v, g_wfl);     p_wfl    = (__nv_bfloat16*)v;
        cudaGetSymbolAddress(&v, g_wprm);    p_wprm   = (__nv_bfloat16*)v;
        cudaGetSymbolAddress(&v, g_wprml);   p_wprml  = (__nv_bfloat16*)v;
        cudaGetSymbolAddress(&v, g_wbh);     p_wbh    = (__nv_bfloat16*)v;
        cudaGetSymbolAddress(&v, g_wbl);     p_wbl    = (__nv_bfloat16*)v;
        cudaGetSymbolAddress(&v, g_wpbrmh);  p_wpbrmh = (__nv_bfloat16*)v;
        cudaGetSymbolAddress(&v, g_wpbrml);  p_wpbrml = (__nv_bfloat16*)v;
        cudaGetSymbolAddress(&v, g_wdbch);   p_wdbch  = (__nv_bfloat16*)v;
        cudaGetSymbolAddress(&v, g_wdbcl);   p_wdbcl  = (__nv_bfloat16*)v;
        cudaGetSymbolAddress(&v, g_wdth);    p_wdth   = (__nv_bfloat16*)v;
        cudaGetSymbolAddress(&v, g_wdtl);    p_wdtl   = (__nv_bfloat16*)v;
        cudaFuncSetAttribute(mma_gemm8<1>,
            cudaFuncAttributeMaxDynamicSharedMemorySize, V8_SMEM);
        cudaFuncSetAttribute(mma_gemm8<4>,
            cudaFuncAttributeMaxDynamicSharedMemorySize, V8_SMEM);
        init = true;
    }

    // ---- prep ----
    ln_kernel<<<BS, 128>>>(x, gamma, beta, p_xnh, p_xnl);
    convert_w<<<(Dc*Dc + 255)/256, 256>>>(W_proj, Dc, Dc, p_wfh, p_wfl); // Wf rows [0,512)
    convert_rm<<<(Dc*Dc + 255)/256, 256>>>(W_proj, Dc*Dc, p_wprm, p_wprml);
    convert_w<<<(Dc*Dc + 255)/256, 256>>>(W_bwd,  Dc, Dc, p_wbh, p_wbl);
    convert_w<<<(Dc*64 + 255)/256, 256>>>(W_dbc,  Dc, 64, p_wdbch, p_wdbcl);
    convert_w<<<(DTR*Dc + 255)/256, 256>>>(W_dt, DTR, Dc, p_wdth, p_wdtl);

    // wgemmC: Wpb[k][j] = sum_i Wp[k][i]*Wb[i][j]; A=wprm [k][i], B=wbh [j][i]
    {
        dim3 g(Dc/64, Dc/64);
        mma_gemm7<64,64,2,4,128><<<g, 128>>>(
            p_wprm, p_wprml, Dc, p_wbh, p_wbl, Dc, nullptr,
            p_afin, p_wpbrmh, p_wpbrml, Dc, Dc, Dc);
    }
    // Wf rows [512,1024): Wf[512+j][k] = Wpb[k][j]  (transpose of wgemmC fp32 out)
    transpose_split<<<(Dc*Dc + 255)/256, 256>>>(p_afin, p_wfh + 512*Dc, p_wfl + 512*Dc);
    // wgemmB: Wf[1024+c][k] = sum_j Wdbc[j][c]*Wpb[k][j]; A=wdbch [c][j], B=wpbrmh [k][j]
    {
        dim3 g(Dc/64, 1);
        mma_gemm7<64,64,2,4,128><<<g, 128>>>(
            p_wdbch, p_wdbcl, Dc, p_wpbrmh, p_wpbrml, Dc, nullptr,
            p_hfin, p_wfh + 1024*Dc, p_wfl + 1024*Dc, 64, Dc, Dc);
    }
    bias2_kernel<<<1, 512>>>(b_proj, W_bwd, b_bwd, p_biasf);
    bias3_kernel<<<1, 128>>>(W_dbc, p_biasf);

    // ---- fused [z1 | bwd | dbc] = xn @ Wf + biasf  (N=1152, grid 9x64) ----
    {
        dim3 g(NFU/128, BS/128);
        mma_gemm8<4><<<g, 128, V8_SMEM>>>(
            p_xnh, p_xnl, Dc, p_wfh, p_wfl, Dc, p_biasf,
            p_z1, p_bwd, nullptr, p_dbc, p_dbch, p_dbcl, BS, NFU, Dc);
    }
    // ---- dt GEMM (K=32) + fused epilogue -> p, du ----
    {
        dim3 g(Dc/128, BS/128);
        mma_gemm8<1><<<g, 128, V8_SMEM>>>(
            p_dbch, p_dbcl, 64, p_wdth, p_wdtl, DTR, b_dt,
            p_p, p_du, p_bwd, nullptr, nullptr, nullptr, BS, Dc, DTR);
    }

    // ---- chunk-parallel SSM scan + fused final elementwise ----
    scan_passA2<<<Bc*NCH*2, 256>>>(p_p, p_du, p_dbc, A_log, p_afin, p_hfin);
    scan_mid<<<(Bc * Dc * Nc) / 256, 256>>>(p_afin, p_hfin, p_h0);
    scan_passB2<<<Bc*NCH*2, 256>>>(p_p, p_du, p_dbc, p_h0,
                                   p_bwd, p_z1, x, A_log, D_ssm, out);
}